// round 12
// baseline (speedup 1.0000x reference)
#include <cuda_runtime.h>
#include <cuda_bf16.h>
#include <cstdint>

#define NB   8
#define LC   2048
#define LQ   1024
#define DIM  768
#define ODIM 1536

static const float kScale = 0.036084391824351614f; // 1/sqrt(768)

// ---------------------------------------------------------------------------
// Scratch (__device__ globals; allocation-free)
// ---------------------------------------------------------------------------
__device__ __nv_bfloat16 g_ch_hi[(size_t)NB * LC * DIM];
__device__ __nv_bfloat16 g_ch_lo[(size_t)NB * LC * DIM];
__device__ __nv_bfloat16 g_qh_hi[(size_t)NB * LQ * DIM];
__device__ __nv_bfloat16 g_qh_lo[(size_t)NB * LQ * DIM];
__device__ __nv_bfloat16 g_qhT_hi[(size_t)NB * DIM * LQ];
__device__ __nv_bfloat16 g_qhT_lo[(size_t)NB * DIM * LQ];
__device__ __nv_bfloat16 g_W_hi[DIM * DIM];
__device__ __nv_bfloat16 g_W_lo[DIM * DIM];
__device__ __nv_bfloat16 g_q_hi[(size_t)NB * LQ * DIM];
__device__ __nv_bfloat16 g_q_lo[(size_t)NB * LQ * DIM];
__device__ float         g_scores[(size_t)NB * LC * LQ];
__device__ __nv_bfloat16 g_p_hi[(size_t)NB * LC * LQ];
__device__ __nv_bfloat16 g_p_lo[(size_t)NB * LC * LQ];

// ---------------------------------------------------------------------------
// Baseline-PTX helpers (no 'a'-suffix features)
// ---------------------------------------------------------------------------
__device__ __forceinline__ uint32_t smem_u32(const void* p) {
    uint32_t a;
    asm("{ .reg .u64 t; cvta.to.shared.u64 t, %1; cvt.u32.u64 %0, t; }"
        : "=r"(a) : "l"(p));
    return a;
}
#define SW128(x) ((x) ^ (((x) >> 3) & 0x70))

#define CP_ASYNC16(dst, src)                                                   \
    asm volatile("cp.async.cg.shared.global [%0], [%1], 16;"                   \
        :: "r"(dst), "l"(src) : "memory")
#define CP_COMMIT() asm volatile("cp.async.commit_group;" ::: "memory")
#define CP_WAIT1() asm volatile("cp.async.wait_group 1;" ::: "memory")
#define CP_WAIT0() asm volatile("cp.async.wait_group 0;" ::: "memory")

#define LDSM_X4(r, addr)                                                       \
    asm volatile("ldmatrix.sync.aligned.m8n8.x4.shared.b16 {%0,%1,%2,%3}, [%4];" \
        : "=r"((r)[0]), "=r"((r)[1]), "=r"((r)[2]), "=r"((r)[3]) : "r"(addr))

#define MMA16816(d, a, b0, b1)                                                 \
    asm volatile(                                                              \
        "mma.sync.aligned.m16n8k16.row.col.f32.bf16.bf16.f32 "                 \
        "{%0,%1,%2,%3},{%4,%5,%6,%7},{%8,%9},{%0,%1,%2,%3};"                   \
        : "+f"((d)[0]), "+f"((d)[1]), "+f"((d)[2]), "+f"((d)[3])               \
        : "r"((a)[0]), "r"((a)[1]), "r"((a)[2]), "r"((a)[3]),                  \
          "r"(b0), "r"(b1))

// CTA tile 128(M) x 256(N), K-stage 64, 3-stage pipeline
static constexpr int STAGE_BYTES = 49152;   // A 16K + B 32K
static constexpr int SMEM_TOTAL = 1024 + 3 * STAGE_BYTES;

// ---------------------------------------------------------------------------
// bf16 mma.sync GEMM:  D[m,n] = sum_k A[m,k]*B[n,k]  (NT, both K-major)
// 3-pass split: A_hi*B_hi + A_hi*B_lo + A_lo*B_hi (register accumulation)
// 8 warps, warp tile 64x64 (4x8 m16n8k16 per k16), single sync per stage.
// EPI: 0 = +bias, split-store bf16 hi/lo (proj)
//      1 = *SCALE, store f32 (scores)
//      2 = store f32 strided (attn -> out)
// ---------------------------------------------------------------------------
template <int EPI>
__global__ __launch_bounds__(256, 1) void gemm_mma(
    const __nv_bfloat16* __restrict__ Ahi, const __nv_bfloat16* __restrict__ Alo, long sA,
    const __nv_bfloat16* __restrict__ Bhi, const __nv_bfloat16* __restrict__ Blo, long sB,
    int K, int ldc, long sC,
    float* __restrict__ Cf,
    __nv_bfloat16* __restrict__ Chi, __nv_bfloat16* __restrict__ Clo,
    const float* __restrict__ bias)
{
    extern __shared__ char smraw[];
    uint32_t sb0 = smem_u32(smraw);
    uint32_t sb = sb0 + ((1024u - (sb0 & 1023u)) & 1023u);

    const int tid = threadIdx.x, wid = tid >> 5, lane = tid & 31;
    const int bx = blockIdx.x, by = blockIdx.y, bz = blockIdx.z;

    const long Abase = bz * sA + (long)by * 128 * K;
    const long Bbase = bz * sB + (long)bx * 256 * K;
    const __nv_bfloat16* Asrc[3] = {Ahi, Ahi, Alo};
    const __nv_bfloat16* Bsrc[3] = {Bhi, Blo, Bhi};

    const int kst = K >> 6;       // 64-elem stages per pass
    const int nst = kst * 3;

    // loader mapping: 16B chunks; A rows 0..127 (4/thread), B rows 0..255 (8/thread)
    const int lrow = tid >> 3;        // base row (+32 per i)
    const int lch = tid & 7;          // 16B chunk in 128B row

    // warp tile 64x64
    const int wm = (wid >> 2) * 64;   // 0 / 64
    const int wn = (wid & 3) * 64;    // 0,64,128,192
    const int lrow16 = (lane & 7) + ((lane >> 3) & 1) * 8; // ldmatrix row-in-16
    const int lkh = (lane >> 4) * 16; // k-half byte offset

    float acc[4][8][4];
    #pragma unroll
    for (int i = 0; i < 4; i++)
        #pragma unroll
        for (int j = 0; j < 8; j++)
            #pragma unroll
            for (int r = 0; r < 4; r++) acc[i][j][r] = 0.0f;

    // ---- issue loads for stage s into buf s%3
    auto issue = [&](int s) {
        const int st = s % 3;
        const uint32_t SA = sb + st * STAGE_BYTES;
        const uint32_t SB = SA + 16384u;
        const int p = s / kst;
        const int kk = (s - p * kst) << 6;
        const __nv_bfloat16* Ap = Asrc[p] + Abase + kk;
        const __nv_bfloat16* Bp = Bsrc[p] + Bbase + kk;
        #pragma unroll
        for (int i = 0; i < 4; i++) {
            const int row = lrow + i * 32;
            const uint32_t off = SW128(row * 128 + lch * 16);
            CP_ASYNC16(SA + off, Ap + (long)row * K + lch * 8);
        }
        #pragma unroll
        for (int i = 0; i < 8; i++) {
            const int row = lrow + i * 32;
            const uint32_t off = SW128(row * 128 + lch * 16);
            CP_ASYNC16(SB + off, Bp + (long)row * K + lch * 8);
        }
        CP_COMMIT();
    };

    issue(0);
    issue(1);
    for (int s = 0; s < nst; s++) {
        if (s == nst - 1) CP_WAIT0(); else CP_WAIT1();
        __syncthreads();
        if (s + 2 < nst) issue(s + 2);

        const int st = s % 3;
        const uint32_t SA = sb + st * STAGE_BYTES;
        const uint32_t SB = SA + 16384u;
        #pragma unroll
        for (int k16 = 0; k16 < 4; k16++) {
            const int kbyte = k16 * 32 + lkh;
            uint32_t afr[4][4];
            #pragma unroll
            for (int i = 0; i < 4; i++) {
                uint32_t addr = SA + SW128((wm + i * 16 + lrow16) * 128 + kbyte);
                LDSM_X4(afr[i], addr);
            }
            uint32_t bfr[4][4];
            #pragma unroll
            for (int j = 0; j < 4; j++) {
                uint32_t addr = SB + SW128((wn + j * 16 + lrow16) * 128 + kbyte);
                LDSM_X4(bfr[j], addr);
            }
            #pragma unroll
            for (int i = 0; i < 4; i++) {
                #pragma unroll
                for (int jj = 0; jj < 8; jj++) {
                    const int j = jj >> 1, o = jj & 1;
                    MMA16816(acc[i][jj], afr[i], bfr[j][o], bfr[j][o + 2]);
                }
            }
        }
    }

    // ---- epilogue: register accums -> global
    const int mrow = lane >> 2;          // 0..7
    const int ncol = (lane & 3) * 2;     // 0,2,4,6
    #pragma unroll
    for (int i = 0; i < 4; i++) {
        #pragma unroll
        for (int jj = 0; jj < 8; jj++) {
            const int n = bx * 256 + wn + jj * 8 + ncol;
            #pragma unroll
            for (int h = 0; h < 2; h++) {  // row / row+8
                const long m = (long)by * 128 + wm + i * 16 + mrow + h * 8;
                const long off = bz * sC + m * ldc + n;
                float v0 = acc[i][jj][2 * h + 0];
                float v1 = acc[i][jj][2 * h + 1];
                if (EPI == 0) {
                    v0 += __ldg(&bias[n]);
                    v1 += __ldg(&bias[n + 1]);
                    __nv_bfloat16 h0 = __float2bfloat16(v0);
                    __nv_bfloat16 h1 = __float2bfloat16(v1);
                    __nv_bfloat16 l0 = __float2bfloat16(v0 - __bfloat162float(h0));
                    __nv_bfloat16 l1 = __float2bfloat16(v1 - __bfloat162float(h1));
                    *(__nv_bfloat162*)(Chi + off) = __halves2bfloat162(h0, h1);
                    *(__nv_bfloat162*)(Clo + off) = __halves2bfloat162(l0, l1);
                } else {
                    const float sc = (EPI == 1) ? kScale : 1.0f;
                    float2 v; v.x = v0 * sc; v.y = v1 * sc;
                    *(float2*)(Cf + off) = v;
                }
            }
        }
    }
}

// ---------------------------------------------------------------------------
// fp32 -> bf16 hi/lo split (elementwise)
// ---------------------------------------------------------------------------
__global__ __launch_bounds__(256) void split_kernel(
    const float* __restrict__ x, __nv_bfloat16* __restrict__ hi,
    __nv_bfloat16* __restrict__ lo)
{
    long i = ((long)blockIdx.x * 256 + threadIdx.x) * 4;
    float4 v = *(const float4*)(x + i);
    __nv_bfloat16 h0 = __float2bfloat16(v.x), h1 = __float2bfloat16(v.y);
    __nv_bfloat16 h2 = __float2bfloat16(v.z), h3 = __float2bfloat16(v.w);
    __nv_bfloat16 l0 = __float2bfloat16(v.x - __bfloat162float(h0));
    __nv_bfloat16 l1 = __float2bfloat16(v.y - __bfloat162float(h1));
    __nv_bfloat16 l2 = __float2bfloat16(v.z - __bfloat162float(h2));
    __nv_bfloat16 l3 = __float2bfloat16(v.w - __bfloat162float(h3));
    ((__nv_bfloat162*)(hi + i))[0] = __halves2bfloat162(h0, h1);
    ((__nv_bfloat162*)(hi + i))[1] = __halves2bfloat162(h2, h3);
    ((__nv_bfloat162*)(lo + i))[0] = __halves2bfloat162(l0, l1);
    ((__nv_bfloat162*)(lo + i))[1] = __halves2bfloat162(l2, l3);
}

// ---------------------------------------------------------------------------
// qh [b, Lq, D] fp32 -> qhT hi/lo [b, D, Lq] bf16 (transpose + split)
// ---------------------------------------------------------------------------
__global__ __launch_bounds__(256) void transpose_split_kernel(
    const float* __restrict__ src, __nv_bfloat16* __restrict__ hiT,
    __nv_bfloat16* __restrict__ loT)
{
    __shared__ float t[32][33];
    const int b = blockIdx.z;
    const int i = blockIdx.x;   // D/32
    const int j = blockIdx.y;   // Lq/32
    const int tx = threadIdx.x & 31, ty = threadIdx.x >> 5;

    const float* s = src + ((long)b * LQ + j * 32) * DIM + i * 32;
    #pragma unroll
    for (int r = 0; r < 4; r++)
        t[ty + 8 * r][tx] = s[(long)(ty + 8 * r) * DIM + tx];
    __syncthreads();

    const long dbase = ((long)b * DIM + i * 32) * LQ + j * 32;
    #pragma unroll
    for (int r = 0; r < 4; r++) {
        float v = t[tx][ty + 8 * r];
        __nv_bfloat16 h = __float2bfloat16(v);
        __nv_bfloat16 l = __float2bfloat16(v - __bfloat162float(h));
        hiT[dbase + (long)(ty + 8 * r) * LQ + tx] = h;
        loT[dbase + (long)(ty + 8 * r) * LQ + tx] = l;
    }
}

// ---------------------------------------------------------------------------
// Masked softmax over q (row len 1024); outputs P as bf16 hi/lo split
// ---------------------------------------------------------------------------
__global__ __launch_bounds__(256) void softmax_kernel(
    const float* __restrict__ S, const int* __restrict__ qmask,
    __nv_bfloat16* __restrict__ Phi, __nv_bfloat16* __restrict__ Plo)
{
    const int row = blockIdx.x;
    const int b = row >> 11;
    const float* s = S + (long)row * LQ;
    const int* msk = qmask + b * LQ;

    const int t = threadIdx.x;
    const int lane = t & 31, warp = t >> 5;

    float4 v = ((const float4*)s)[t];
    int4 m = ((const int4*)msk)[t];
    float x0 = m.x ? v.x : -1e30f;
    float x1 = m.y ? v.y : -1e30f;
    float x2 = m.z ? v.z : -1e30f;
    float x3 = m.w ? v.w : -1e30f;

    __shared__ float sh[8];
    __shared__ float shv[2];

    float mx = fmaxf(fmaxf(x0, x1), fmaxf(x2, x3));
    #pragma unroll
    for (int off = 16; off > 0; off >>= 1)
        mx = fmaxf(mx, __shfl_xor_sync(0xffffffffu, mx, off));
    if (lane == 0) sh[warp] = mx;
    __syncthreads();
    if (t == 0) {
        float r = sh[0];
        #pragma unroll
        for (int i = 1; i < 8; i++) r = fmaxf(r, sh[i]);
        shv[0] = r;
    }
    __syncthreads();
    mx = shv[0];

    float e0 = m.x ? __expf(x0 - mx) : 0.0f;
    float e1 = m.y ? __expf(x1 - mx) : 0.0f;
    float e2 = m.z ? __expf(x2 - mx) : 0.0f;
    float e3 = m.w ? __expf(x3 - mx) : 0.0f;
    float sum = e0 + e1 + e2 + e3;
    #pragma unroll
    for (int off = 16; off > 0; off >>= 1)
        sum += __shfl_xor_sync(0xffffffffu, sum, off);
    __syncthreads();
    if (lane == 0) sh[warp] = sum;
    __syncthreads();
    if (t == 0) {
        float r = 0.0f;
        #pragma unroll
        for (int i = 0; i < 8; i++) r += sh[i];
        shv[1] = r;
    }
    __syncthreads();
    float inv = 1.0f / shv[1];

    float p0 = e0 * inv, p1 = e1 * inv, p2 = e2 * inv, p3 = e3 * inv;
    __nv_bfloat16 h0 = __float2bfloat16(p0), h1 = __float2bfloat16(p1);
    __nv_bfloat16 h2 = __float2bfloat16(p2), h3 = __float2bfloat16(p3);
    __nv_bfloat16 l0 = __float2bfloat16(p0 - __bfloat162float(h0));
    __nv_bfloat16 l1 = __float2bfloat16(p1 - __bfloat162float(h1));
    __nv_bfloat16 l2 = __float2bfloat16(p2 - __bfloat162float(h2));
    __nv_bfloat16 l3 = __float2bfloat16(p3 - __bfloat162float(h3));
    long base = (long)row * LQ + t * 4;
    ((__nv_bfloat162*)(Phi + base))[0] = __halves2bfloat162(h0, h1);
    ((__nv_bfloat162*)(Phi + base))[1] = __halves2bfloat162(h2, h3);
    ((__nv_bfloat162*)(Plo + base))[0] = __halves2bfloat162(l0, l1);
    ((__nv_bfloat162*)(Plo + base))[1] = __halves2bfloat162(l2, l3);
}

// ---------------------------------------------------------------------------
// out[..., 0:768] = context_hiddens
// ---------------------------------------------------------------------------
__global__ __launch_bounds__(256) void copy_ctx_kernel(
    const float* __restrict__ chx, float* __restrict__ out)
{
    long idx = (long)blockIdx.x * blockDim.x + threadIdx.x;
    float4 v = ((const float4*)chx)[idx];
    long row = idx / 192;
    long c4 = idx % 192;
    ((float4*)out)[row * 384 + c4] = v;
}

// ---------------------------------------------------------------------------
extern "C" void kernel_launch(void* const* d_in, const int* in_sizes, int n_in,
                              void* d_out, int out_size)
{
    (void)in_sizes; (void)n_in; (void)out_size;
    const float* chx   = (const float*)d_in[0];
    const float* qh    = (const float*)d_in[2];
    const int*   qmask = (const int*)d_in[3];
    const float* W     = (const float*)d_in[4];
    const float* bvec  = (const float*)d_in[5];
    float* out = (float*)d_out;

    cudaFuncSetAttribute(gemm_mma<0>, cudaFuncAttributeMaxDynamicSharedMemorySize, SMEM_TOTAL);
    cudaFuncSetAttribute(gemm_mma<1>, cudaFuncAttributeMaxDynamicSharedMemorySize, SMEM_TOTAL);
    cudaFuncSetAttribute(gemm_mma<2>, cudaFuncAttributeMaxDynamicSharedMemorySize, SMEM_TOTAL);

    __nv_bfloat16 *ch_hi, *ch_lo, *qh_hi, *qh_lo, *qhT_hi, *qhT_lo;
    __nv_bfloat16 *W_hi, *W_lo, *q_hi, *q_lo, *p_hi, *p_lo;
    float* scores;
    cudaGetSymbolAddress((void**)&ch_hi,  g_ch_hi);
    cudaGetSymbolAddress((void**)&ch_lo,  g_ch_lo);
    cudaGetSymbolAddress((void**)&qh_hi,  g_qh_hi);
    cudaGetSymbolAddress((void**)&qh_lo,  g_qh_lo);
    cudaGetSymbolAddress((void**)&qhT_hi, g_qhT_hi);
    cudaGetSymbolAddress((void**)&qhT_lo, g_qhT_lo);
    cudaGetSymbolAddress((void**)&W_hi,   g_W_hi);
    cudaGetSymbolAddress((void**)&W_lo,   g_W_lo);
    cudaGetSymbolAddress((void**)&q_hi,   g_q_hi);
    cudaGetSymbolAddress((void**)&q_lo,   g_q_lo);
    cudaGetSymbolAddress((void**)&p_hi,   g_p_hi);
    cudaGetSymbolAddress((void**)&p_lo,   g_p_lo);
    cudaGetSymbolAddress((void**)&scores, g_scores);

    // splits
    split_kernel<<<12288, 256>>>(chx, ch_hi, ch_lo);
    split_kernel<<<6144, 256>>>(qh, qh_hi, qh_lo);
    split_kernel<<<576, 256>>>(W, W_hi, W_lo);
    transpose_split_kernel<<<dim3(DIM / 32, LQ / 32, NB), 256>>>(qh, qhT_hi, qhT_lo);

    // 1) query = qh @ W^T + b  -> split bf16   (M=8192, N=768, K=768)
    gemm_mma<0><<<dim3(3, 64, 1), 256, SMEM_TOTAL>>>(
        qh_hi, qh_lo, 0L, W_hi, W_lo, 0L,
        DIM, DIM, 0L, nullptr, q_hi, q_lo, bvec);

    // 2) scores = ch @ query^T * SCALE  (per b: M=2048, N=1024, K=768)
    gemm_mma<1><<<dim3(4, 16, NB), 256, SMEM_TOTAL>>>(
        ch_hi, ch_lo, (long)LC * DIM,
        q_hi, q_lo, (long)LQ * DIM,
        DIM, LQ, (long)LC * LQ, scores, nullptr, nullptr, nullptr);

    // 3) masked softmax -> P hi/lo
    softmax_kernel<<<NB * LC, 256>>>(scores, qmask, p_hi, p_lo);

    // 4) attn = P @ qh  (per b: M=2048, N=768, K=1024) -> out[..., 768:]
    gemm_mma<2><<<dim3(3, 16, NB), 256, SMEM_TOTAL>>>(
        p_hi, p_lo, (long)LC * LQ,
        qhT_hi, qhT_lo, (long)DIM * LQ,
        LQ, ODIM, (long)LC * ODIM, out + DIM, nullptr, nullptr, nullptr);

    // 5) out[..., 0:768] = context_hiddens
    copy_ctx_kernel<<<12288, 256>>>(chx, out);
}

// round 13
// speedup vs baseline: 1.1033x; 1.1033x over previous
#include <cuda_runtime.h>
#include <cuda_bf16.h>
#include <cstdint>

#define NB   8
#define LC   2048
#define LQ   1024
#define DIM  768
#define ODIM 1536

static const float kScale = 0.036084391824351614f; // 1/sqrt(768)

// ---------------------------------------------------------------------------
// Scratch (__device__ globals; allocation-free)
// ---------------------------------------------------------------------------
__device__ __nv_bfloat16 g_ch_hi[(size_t)NB * LC * DIM];
__device__ __nv_bfloat16 g_ch_lo[(size_t)NB * LC * DIM];
__device__ __nv_bfloat16 g_qh_hi[(size_t)NB * LQ * DIM];
__device__ __nv_bfloat16 g_qh_lo[(size_t)NB * LQ * DIM];
__device__ __nv_bfloat16 g_qhT_hi[(size_t)NB * DIM * LQ];
__device__ __nv_bfloat16 g_qhT_lo[(size_t)NB * DIM * LQ];
__device__ __nv_bfloat16 g_W_hi[DIM * DIM];
__device__ __nv_bfloat16 g_W_lo[DIM * DIM];
__device__ __nv_bfloat16 g_q_hi[(size_t)NB * LQ * DIM];
__device__ __nv_bfloat16 g_q_lo[(size_t)NB * LQ * DIM];
__device__ float         g_scores[(size_t)NB * LC * LQ];
__device__ __nv_bfloat16 g_p_hi[(size_t)NB * LC * LQ];
__device__ __nv_bfloat16 g_p_lo[(size_t)NB * LC * LQ];

// ---------------------------------------------------------------------------
// Baseline-PTX helpers (no 'a'-suffix features)
// ---------------------------------------------------------------------------
__device__ __forceinline__ uint32_t smem_u32(const void* p) {
    uint32_t a;
    asm("{ .reg .u64 t; cvta.to.shared.u64 t, %1; cvt.u32.u64 %0, t; }"
        : "=r"(a) : "l"(p));
    return a;
}
#define SW128(x) ((x) ^ (((x) >> 3) & 0x70))

#define CP_ASYNC16(dst, src)                                                   \
    asm volatile("cp.async.cg.shared.global [%0], [%1], 16;"                   \
        :: "r"(dst), "l"(src) : "memory")
#define CP_COMMIT() asm volatile("cp.async.commit_group;" ::: "memory")
#define CP_WAIT1() asm volatile("cp.async.wait_group 1;" ::: "memory")
#define CP_WAIT0() asm volatile("cp.async.wait_group 0;" ::: "memory")

#define LDSM_X4(r, addr)                                                       \
    asm volatile("ldmatrix.sync.aligned.m8n8.x4.shared.b16 {%0,%1,%2,%3}, [%4];" \
        : "=r"((r)[0]), "=r"((r)[1]), "=r"((r)[2]), "=r"((r)[3]) : "r"(addr))

#define MMA16816(d, a, b0, b1)                                                 \
    asm volatile(                                                              \
        "mma.sync.aligned.m16n8k16.row.col.f32.bf16.bf16.f32 "                 \
        "{%0,%1,%2,%3},{%4,%5,%6,%7},{%8,%9},{%0,%1,%2,%3};"                   \
        : "+f"((d)[0]), "+f"((d)[1]), "+f"((d)[2]), "+f"((d)[3])               \
        : "r"((a)[0]), "r"((a)[1]), "r"((a)[2]), "r"((a)[3]),                  \
          "r"(b0), "r"(b1))

// CTA tile 128x128, K-stage 64, 3-stage pipeline (A 16K + B 16K per stage)
static constexpr int STAGE_BYTES = 32768;
static constexpr int SMEM_TOTAL = 1024 + 3 * STAGE_BYTES;   // 99 KB -> 2 CTAs/SM

// ---------------------------------------------------------------------------
// bf16 mma.sync GEMM:  D[m,n] = sum_k A[m,k]*B[n,k]  (NT, both K-major)
// 3-pass split: A_hi*B_hi + A_hi*B_lo + A_lo*B_hi (register accumulation)
// 8 warps, warp tile 64x32, single __syncthreads per stage, prefetch 2 ahead.
// EPI: 0 = +bias, split-store bf16 hi/lo (proj)
//      1 = *SCALE, store f32 (scores)
//      2 = store f32 strided (attn -> out)
// ---------------------------------------------------------------------------
template <int EPI>
__global__ __launch_bounds__(256, 2) void gemm_mma(
    const __nv_bfloat16* __restrict__ Ahi, const __nv_bfloat16* __restrict__ Alo, long sA,
    const __nv_bfloat16* __restrict__ Bhi, const __nv_bfloat16* __restrict__ Blo, long sB,
    int K, int ldc, long sC,
    float* __restrict__ Cf,
    __nv_bfloat16* __restrict__ Chi, __nv_bfloat16* __restrict__ Clo,
    const float* __restrict__ bias)
{
    extern __shared__ char smraw[];
    uint32_t sb0 = smem_u32(smraw);
    uint32_t sb = sb0 + ((1024u - (sb0 & 1023u)) & 1023u);

    const int tid = threadIdx.x, wid = tid >> 5, lane = tid & 31;
    const int bx = blockIdx.x, by = blockIdx.y, bz = blockIdx.z;

    const long Abase = bz * sA + (long)by * 128 * K;
    const long Bbase = bz * sB + (long)bx * 128 * K;
    const __nv_bfloat16* Asrc[3] = {Ahi, Ahi, Alo};
    const __nv_bfloat16* Bsrc[3] = {Bhi, Blo, Bhi};

    const int kst = K >> 6;       // 64-elem stages per pass
    const int nst = kst * 3;

    // loader mapping: 4 chunks of A + 4 of B per thread per stage
    const int lrow = tid >> 3;        // 0..31 (+32 per i)
    const int lch = tid & 7;          // 16B chunk in 128B row

    // warp tile 64x32
    const int wm = (wid >> 2) * 64;   // 0 / 64
    const int wn = (wid & 3) * 32;    // 0,32,64,96
    const int lrow16 = (lane & 7) + ((lane >> 3) & 1) * 8; // ldmatrix row-in-16
    const int lkh = (lane >> 4) * 16; // k-half byte offset

    float acc[4][4][4];
    #pragma unroll
    for (int i = 0; i < 4; i++)
        #pragma unroll
        for (int j = 0; j < 4; j++)
            #pragma unroll
            for (int r = 0; r < 4; r++) acc[i][j][r] = 0.0f;

    // ---- issue loads for stage s into buf s%3
    auto issue = [&](int s) {
        const int st = s % 3;
        const uint32_t SA = sb + st * STAGE_BYTES;
        const uint32_t SB = SA + 16384u;
        const int p = s / kst;
        const int kk = (s - p * kst) << 6;
        const __nv_bfloat16* Ap = Asrc[p] + Abase + kk;
        const __nv_bfloat16* Bp = Bsrc[p] + Bbase + kk;
        #pragma unroll
        for (int i = 0; i < 4; i++) {
            const int row = lrow + i * 32;
            const uint32_t off = SW128(row * 128 + lch * 16);
            CP_ASYNC16(SA + off, Ap + (long)row * K + lch * 8);
            CP_ASYNC16(SB + off, Bp + (long)row * K + lch * 8);
        }
        CP_COMMIT();
    };

    issue(0);
    issue(1);
    for (int s = 0; s < nst; s++) {
        if (s == nst - 1) CP_WAIT0(); else CP_WAIT1();
        __syncthreads();                 // stage s ready AND compute(s-1) done
        if (s + 2 < nst) issue(s + 2);   // safe: overwrites buf (s-1)%3

        const int st = s % 3;
        const uint32_t SA = sb + st * STAGE_BYTES;
        const uint32_t SB = SA + 16384u;
        #pragma unroll
        for (int k16 = 0; k16 < 4; k16++) {
            const int kbyte = k16 * 32 + lkh;
            uint32_t afr[4][4];
            #pragma unroll
            for (int i = 0; i < 4; i++) {
                uint32_t addr = SA + SW128((wm + i * 16 + lrow16) * 128 + kbyte);
                LDSM_X4(afr[i], addr);
            }
            uint32_t bfr[2][4];
            #pragma unroll
            for (int j = 0; j < 2; j++) {
                uint32_t addr = SB + SW128((wn + j * 16 + lrow16) * 128 + kbyte);
                LDSM_X4(bfr[j], addr);
            }
            #pragma unroll
            for (int i = 0; i < 4; i++) {
                #pragma unroll
                for (int jj = 0; jj < 4; jj++) {
                    const int j = jj >> 1, o = jj & 1;
                    MMA16816(acc[i][jj], afr[i], bfr[j][o], bfr[j][o + 2]);
                }
            }
        }
    }

    // ---- epilogue: register accums -> global
    const int mrow = lane >> 2;          // 0..7
    const int ncol = (lane & 3) * 2;     // 0,2,4,6
    #pragma unroll
    for (int i = 0; i < 4; i++) {
        #pragma unroll
        for (int jj = 0; jj < 4; jj++) {
            const int n = bx * 128 + wn + jj * 8 + ncol;
            #pragma unroll
            for (int h = 0; h < 2; h++) {  // row / row+8
                const long m = (long)by * 128 + wm + i * 16 + mrow + h * 8;
                const long off = bz * sC + m * ldc + n;
                float v0 = acc[i][jj][2 * h + 0];
                float v1 = acc[i][jj][2 * h + 1];
                if (EPI == 0) {
                    v0 += __ldg(&bias[n]);
                    v1 += __ldg(&bias[n + 1]);
                    __nv_bfloat16 h0 = __float2bfloat16(v0);
                    __nv_bfloat16 h1 = __float2bfloat16(v1);
                    __nv_bfloat16 l0 = __float2bfloat16(v0 - __bfloat162float(h0));
                    __nv_bfloat16 l1 = __float2bfloat16(v1 - __bfloat162float(h1));
                    *(__nv_bfloat162*)(Chi + off) = __halves2bfloat162(h0, h1);
                    *(__nv_bfloat162*)(Clo + off) = __halves2bfloat162(l0, l1);
                } else {
                    const float sc = (EPI == 1) ? kScale : 1.0f;
                    float2 v; v.x = v0 * sc; v.y = v1 * sc;
                    *(float2*)(Cf + off) = v;
                }
            }
        }
    }
}

// ---------------------------------------------------------------------------
// fp32 -> bf16 hi/lo split (elementwise)
// ---------------------------------------------------------------------------
__global__ __launch_bounds__(256) void split_kernel(
    const float* __restrict__ x, __nv_bfloat16* __restrict__ hi,
    __nv_bfloat16* __restrict__ lo)
{
    long i = ((long)blockIdx.x * 256 + threadIdx.x) * 4;
    float4 v = *(const float4*)(x + i);
    __nv_bfloat16 h0 = __float2bfloat16(v.x), h1 = __float2bfloat16(v.y);
    __nv_bfloat16 h2 = __float2bfloat16(v.z), h3 = __float2bfloat16(v.w);
    __nv_bfloat16 l0 = __float2bfloat16(v.x - __bfloat162float(h0));
    __nv_bfloat16 l1 = __float2bfloat16(v.y - __bfloat162float(h1));
    __nv_bfloat16 l2 = __float2bfloat16(v.z - __bfloat162float(h2));
    __nv_bfloat16 l3 = __float2bfloat16(v.w - __bfloat162float(h3));
    ((__nv_bfloat162*)(hi + i))[0] = __halves2bfloat162(h0, h1);
    ((__nv_bfloat162*)(hi + i))[1] = __halves2bfloat162(h2, h3);
    ((__nv_bfloat162*)(lo + i))[0] = __halves2bfloat162(l0, l1);
    ((__nv_bfloat162*)(lo + i))[1] = __halves2bfloat162(l2, l3);
}

// ---------------------------------------------------------------------------
// qh [b, Lq, D] fp32 -> qhT hi/lo [b, D, Lq] bf16 (transpose + split)
// ---------------------------------------------------------------------------
__global__ __launch_bounds__(256) void transpose_split_kernel(
    const float* __restrict__ src, __nv_bfloat16* __restrict__ hiT,
    __nv_bfloat16* __restrict__ loT)
{
    __shared__ float t[32][33];
    const int b = blockIdx.z;
    const int i = blockIdx.x;   // D/32
    const int j = blockIdx.y;   // Lq/32
    const int tx = threadIdx.x & 31, ty = threadIdx.x >> 5;

    const float* s = src + ((long)b * LQ + j * 32) * DIM + i * 32;
    #pragma unroll
    for (int r = 0; r < 4; r++)
        t[ty + 8 * r][tx] = s[(long)(ty + 8 * r) * DIM + tx];
    __syncthreads();

    const long dbase = ((long)b * DIM + i * 32) * LQ + j * 32;
    #pragma unroll
    for (int r = 0; r < 4; r++) {
        float v = t[tx][ty + 8 * r];
        __nv_bfloat16 h = __float2bfloat16(v);
        __nv_bfloat16 l = __float2bfloat16(v - __bfloat162float(h));
        hiT[dbase + (long)(ty + 8 * r) * LQ + tx] = h;
        loT[dbase + (long)(ty + 8 * r) * LQ + tx] = l;
    }
}

// ---------------------------------------------------------------------------
// Masked softmax over q (row len 1024); outputs P as bf16 hi/lo split
// ---------------------------------------------------------------------------
__global__ __launch_bounds__(256) void softmax_kernel(
    const float* __restrict__ S, const int* __restrict__ qmask,
    __nv_bfloat16* __restrict__ Phi, __nv_bfloat16* __restrict__ Plo)
{
    const int row = blockIdx.x;
    const int b = row >> 11;
    const float* s = S + (long)row * LQ;
    const int* msk = qmask + b * LQ;

    const int t = threadIdx.x;
    const int lane = t & 31, warp = t >> 5;

    float4 v = ((const float4*)s)[t];
    int4 m = ((const int4*)msk)[t];
    float x0 = m.x ? v.x : -1e30f;
    float x1 = m.y ? v.y : -1e30f;
    float x2 = m.z ? v.z : -1e30f;
    float x3 = m.w ? v.w : -1e30f;

    __shared__ float sh[8];
    __shared__ float shv[2];

    float mx = fmaxf(fmaxf(x0, x1), fmaxf(x2, x3));
    #pragma unroll
    for (int off = 16; off > 0; off >>= 1)
        mx = fmaxf(mx, __shfl_xor_sync(0xffffffffu, mx, off));
    if (lane == 0) sh[warp] = mx;
    __syncthreads();
    if (t == 0) {
        float r = sh[0];
        #pragma unroll
        for (int i = 1; i < 8; i++) r = fmaxf(r, sh[i]);
        shv[0] = r;
    }
    __syncthreads();
    mx = shv[0];

    float e0 = m.x ? __expf(x0 - mx) : 0.0f;
    float e1 = m.y ? __expf(x1 - mx) : 0.0f;
    float e2 = m.z ? __expf(x2 - mx) : 0.0f;
    float e3 = m.w ? __expf(x3 - mx) : 0.0f;
    float sum = e0 + e1 + e2 + e3;
    #pragma unroll
    for (int off = 16; off > 0; off >>= 1)
        sum += __shfl_xor_sync(0xffffffffu, sum, off);
    __syncthreads();
    if (lane == 0) sh[warp] = sum;
    __syncthreads();
    if (t == 0) {
        float r = 0.0f;
        #pragma unroll
        for (int i = 0; i < 8; i++) r += sh[i];
        shv[1] = r;
    }
    __syncthreads();
    float inv = 1.0f / shv[1];

    float p0 = e0 * inv, p1 = e1 * inv, p2 = e2 * inv, p3 = e3 * inv;
    __nv_bfloat16 h0 = __float2bfloat16(p0), h1 = __float2bfloat16(p1);
    __nv_bfloat16 h2 = __float2bfloat16(p2), h3 = __float2bfloat16(p3);
    __nv_bfloat16 l0 = __float2bfloat16(p0 - __bfloat162float(h0));
    __nv_bfloat16 l1 = __float2bfloat16(p1 - __bfloat162float(h1));
    __nv_bfloat16 l2 = __float2bfloat16(p2 - __bfloat162float(h2));
    __nv_bfloat16 l3 = __float2bfloat16(p3 - __bfloat162float(h3));
    long base = (long)row * LQ + t * 4;
    ((__nv_bfloat162*)(Phi + base))[0] = __halves2bfloat162(h0, h1);
    ((__nv_bfloat162*)(Phi + base))[1] = __halves2bfloat162(h2, h3);
    ((__nv_bfloat162*)(Plo + base))[0] = __halves2bfloat162(l0, l1);
    ((__nv_bfloat162*)(Plo + base))[1] = __halves2bfloat162(l2, l3);
}

// ---------------------------------------------------------------------------
// out[..., 0:768] = context_hiddens
// ---------------------------------------------------------------------------
__global__ __launch_bounds__(256) void copy_ctx_kernel(
    const float* __restrict__ chx, float* __restrict__ out)
{
    long idx = (long)blockIdx.x * blockDim.x + threadIdx.x;
    float4 v = ((const float4*)chx)[idx];
    long row = idx / 192;
    long c4 = idx % 192;
    ((float4*)out)[row * 384 + c4] = v;
}

// ---------------------------------------------------------------------------
extern "C" void kernel_launch(void* const* d_in, const int* in_sizes, int n_in,
                              void* d_out, int out_size)
{
    (void)in_sizes; (void)n_in; (void)out_size;
    const float* chx   = (const float*)d_in[0];
    const float* qh    = (const float*)d_in[2];
    const int*   qmask = (const int*)d_in[3];
    const float* W     = (const float*)d_in[4];
    const float* bvec  = (const float*)d_in[5];
    float* out = (float*)d_out;

    cudaFuncSetAttribute(gemm_mma<0>, cudaFuncAttributeMaxDynamicSharedMemorySize, SMEM_TOTAL);
    cudaFuncSetAttribute(gemm_mma<1>, cudaFuncAttributeMaxDynamicSharedMemorySize, SMEM_TOTAL);
    cudaFuncSetAttribute(gemm_mma<2>, cudaFuncAttributeMaxDynamicSharedMemorySize, SMEM_TOTAL);

    __nv_bfloat16 *ch_hi, *ch_lo, *qh_hi, *qh_lo, *qhT_hi, *qhT_lo;
    __nv_bfloat16 *W_hi, *W_lo, *q_hi, *q_lo, *p_hi, *p_lo;
    float* scores;
    cudaGetSymbolAddress((void**)&ch_hi,  g_ch_hi);
    cudaGetSymbolAddress((void**)&ch_lo,  g_ch_lo);
    cudaGetSymbolAddress((void**)&qh_hi,  g_qh_hi);
    cudaGetSymbolAddress((void**)&qh_lo,  g_qh_lo);
    cudaGetSymbolAddress((void**)&qhT_hi, g_qhT_hi);
    cudaGetSymbolAddress((void**)&qhT_lo, g_qhT_lo);
    cudaGetSymbolAddress((void**)&W_hi,   g_W_hi);
    cudaGetSymbolAddress((void**)&W_lo,   g_W_lo);
    cudaGetSymbolAddress((void**)&q_hi,   g_q_hi);
    cudaGetSymbolAddress((void**)&q_lo,   g_q_lo);
    cudaGetSymbolAddress((void**)&p_hi,   g_p_hi);
    cudaGetSymbolAddress((void**)&p_lo,   g_p_lo);
    cudaGetSymbolAddress((void**)&scores, g_scores);

    // splits
    split_kernel<<<12288, 256>>>(chx, ch_hi, ch_lo);
    split_kernel<<<6144, 256>>>(qh, qh_hi, qh_lo);
    split_kernel<<<576, 256>>>(W, W_hi, W_lo);
    transpose_split_kernel<<<dim3(DIM / 32, LQ / 32, NB), 256>>>(qh, qhT_hi, qhT_lo);

    // 1) query = qh @ W^T + b  -> split bf16   (M=8192, N=768, K=768)
    gemm_mma<0><<<dim3(6, 64, 1), 256, SMEM_TOTAL>>>(
        qh_hi, qh_lo, 0L, W_hi, W_lo, 0L,
        DIM, DIM, 0L, nullptr, q_hi, q_lo, bvec);

    // 2) scores = ch @ query^T * SCALE  (per b: M=2048, N=1024, K=768)
    gemm_mma<1><<<dim3(8, 16, NB), 256, SMEM_TOTAL>>>(
        ch_hi, ch_lo, (long)LC * DIM,
        q_hi, q_lo, (long)LQ * DIM,
        DIM, LQ, (long)LC * LQ, scores, nullptr, nullptr, nullptr);

    // 3) masked softmax -> P hi/lo
    softmax_kernel<<<NB * LC, 256>>>(scores, qmask, p_hi, p_lo);

    // 4) attn = P @ qh  (per b: M=2048, N=768, K=1024) -> out[..., 768:]
    gemm_mma<2><<<dim3(6, 16, NB), 256, SMEM_TOTAL>>>(
        p_hi, p_lo, (long)LC * LQ,
        qhT_hi, qhT_lo, (long)DIM * LQ,
        LQ, ODIM, (long)LC * ODIM, out + DIM, nullptr, nullptr, nullptr);

    // 5) out[..., 0:768] = context_hiddens
    copy_ctx_kernel<<<12288, 256>>>(chx, out);
}

// round 17
// speedup vs baseline: 1.1727x; 1.0629x over previous
#include <cuda_runtime.h>
#include <cuda_bf16.h>
#include <cstdint>

#define NB   8
#define LC   2048
#define LQ   1024
#define DIM  768
#define ODIM 1536

static const float kScale = 0.036084391824351614f; // 1/sqrt(768)

// ---------------------------------------------------------------------------
// Scratch (__device__ globals; allocation-free)
// ---------------------------------------------------------------------------
__device__ __nv_bfloat16 g_ch_hi[(size_t)NB * LC * DIM];
__device__ __nv_bfloat16 g_ch_lo[(size_t)NB * LC * DIM];
__device__ __nv_bfloat16 g_qh_hi[(size_t)NB * LQ * DIM];
__device__ __nv_bfloat16 g_qh_lo[(size_t)NB * LQ * DIM];
__device__ __nv_bfloat16 g_qhT_hi[(size_t)NB * DIM * LQ];
__device__ __nv_bfloat16 g_qhT_lo[(size_t)NB * DIM * LQ];
__device__ __nv_bfloat16 g_W_hi[DIM * DIM];
__device__ __nv_bfloat16 g_W_lo[DIM * DIM];
__device__ __nv_bfloat16 g_q_hi[(size_t)NB * LQ * DIM];
__device__ __nv_bfloat16 g_q_lo[(size_t)NB * LQ * DIM];
__device__ float         g_scores[(size_t)NB * LC * LQ];
__device__ __nv_bfloat16 g_p_hi[(size_t)NB * LC * LQ];
__device__ __nv_bfloat16 g_p_lo[(size_t)NB * LC * LQ];

// ---------------------------------------------------------------------------
// Baseline-PTX helpers (no 'a'-suffix features)
// ---------------------------------------------------------------------------
__device__ __forceinline__ uint32_t smem_u32(const void* p) {
    uint32_t a;
    asm("{ .reg .u64 t; cvta.to.shared.u64 t, %1; cvt.u32.u64 %0, t; }"
        : "=r"(a) : "l"(p));
    return a;
}
#define SW128(x) ((x) ^ (((x) >> 3) & 0x70))

#define CP_ASYNC16(dst, src)                                                   \
    asm volatile("cp.async.cg.shared.global [%0], [%1], 16;"                   \
        :: "r"(dst), "l"(src) : "memory")
#define CP_COMMIT() asm volatile("cp.async.commit_group;" ::: "memory")
#define CP_WAIT1() asm volatile("cp.async.wait_group 1;" ::: "memory")
#define CP_WAIT0() asm volatile("cp.async.wait_group 0;" ::: "memory")

#define LDSM_X4(r, addr)                                                       \
    asm volatile("ldmatrix.sync.aligned.m8n8.x4.shared.b16 {%0,%1,%2,%3}, [%4];" \
        : "=r"((r)[0]), "=r"((r)[1]), "=r"((r)[2]), "=r"((r)[3]) : "r"(addr))

#define MMA16816(d, a, b0, b1)                                                 \
    asm volatile(                                                              \
        "mma.sync.aligned.m16n8k16.row.col.f32.bf16.bf16.f32 "                 \
        "{%0,%1,%2,%3},{%4,%5,%6,%7},{%8,%9},{%0,%1,%2,%3};"                   \
        : "+f"((d)[0]), "+f"((d)[1]), "+f"((d)[2]), "+f"((d)[3])               \
        : "r"((a)[0]), "r"((a)[1]), "r"((a)[2]), "r"((a)[3]),                  \
          "r"(b0), "r"(b1))

// CTA tile 128x128, K-stage 64, 2-stage double buffer (A 16K + B 16K per stage)
static constexpr int STAGE_BYTES = 32768;
static constexpr int SMEM_TOTAL = 1024 + 2 * STAGE_BYTES;   // 66 KB -> 2 CTAs/SM

// ---------------------------------------------------------------------------
// bf16 mma.sync GEMM:  D[m,n] = sum_k A[m,k]*B[n,k]  (NT, both K-major)
// 3-pass split: A_hi*B_hi + A_hi*B_lo + A_lo*B_hi (register accumulation)
// 128 threads (4 warps), warp tile 64x64 -> 8 LDSM per 32 MMA per k16.
// EPI: 0 = +bias, split-store bf16 hi/lo (proj)
//      1 = *SCALE, store f32 (scores)
//      2 = store f32 strided (attn -> out)
// ---------------------------------------------------------------------------
template <int EPI>
__global__ __launch_bounds__(128, 2) void gemm_mma(
    const __nv_bfloat16* __restrict__ Ahi, const __nv_bfloat16* __restrict__ Alo, long sA,
    const __nv_bfloat16* __restrict__ Bhi, const __nv_bfloat16* __restrict__ Blo, long sB,
    int K, int ldc, long sC,
    float* __restrict__ Cf,
    __nv_bfloat16* __restrict__ Chi, __nv_bfloat16* __restrict__ Clo,
    const float* __restrict__ bias)
{
    extern __shared__ char smraw[];
    uint32_t sb0 = smem_u32(smraw);
    uint32_t sb = sb0 + ((1024u - (sb0 & 1023u)) & 1023u);

    const int tid = threadIdx.x, wid = tid >> 5, lane = tid & 31;
    const int bx = blockIdx.x, by = blockIdx.y, bz = blockIdx.z;

    const long Abase = bz * sA + (long)by * 128 * K;
    const long Bbase = bz * sB + (long)bx * 128 * K;
    const __nv_bfloat16* Asrc[3] = {Ahi, Ahi, Alo};
    const __nv_bfloat16* Bsrc[3] = {Bhi, Blo, Bhi};

    const int kst = K >> 6;       // 64-elem stages per pass
    const int nst = kst * 3;

    // loader mapping (128 threads): 8 chunks of A + 8 of B per thread per stage
    const int lrow = tid >> 3;        // 0..15 (+16 per i)
    const int lch = tid & 7;          // 16B chunk in 128B row

    // warp tile 64x64
    const int wm = (wid >> 1) * 64;   // 0 / 64
    const int wn = (wid & 1) * 64;    // 0 / 64
    const int lrow16 = (lane & 7) + ((lane >> 3) & 1) * 8; // ldmatrix row-in-16
    const int lkh = (lane >> 4) * 16; // k-half byte offset

    float acc[4][8][4];
    #pragma unroll
    for (int i = 0; i < 4; i++)
        #pragma unroll
        for (int j = 0; j < 8; j++)
            #pragma unroll
            for (int r = 0; r < 4; r++) acc[i][j][r] = 0.0f;

    // ---- issue loads for stage s into buf s&1
    auto issue = [&](int s) {
        const int st = s & 1;
        const uint32_t SA = sb + st * STAGE_BYTES;
        const uint32_t SB = SA + 16384u;
        const int p = s / kst;
        const int kk = (s - p * kst) << 6;
        const __nv_bfloat16* Ap = Asrc[p] + Abase + kk;
        const __nv_bfloat16* Bp = Bsrc[p] + Bbase + kk;
        #pragma unroll
        for (int i = 0; i < 8; i++) {
            const int row = lrow + i * 16;
            const uint32_t off = SW128(row * 128 + lch * 16);
            CP_ASYNC16(SA + off, Ap + (long)row * K + lch * 8);
            CP_ASYNC16(SB + off, Bp + (long)row * K + lch * 8);
        }
        CP_COMMIT();
    };

    issue(0);
    for (int s = 0; s < nst; s++) {
        if (s + 1 < nst) { issue(s + 1); CP_WAIT1(); }
        else             { CP_WAIT0(); }
        __syncthreads();

        const int st = s & 1;
        const uint32_t SA = sb + st * STAGE_BYTES;
        const uint32_t SB = SA + 16384u;
        #pragma unroll
        for (int k16 = 0; k16 < 4; k16++) {
            const int kbyte = k16 * 32 + lkh;
            uint32_t afr[4][4];
            #pragma unroll
            for (int i = 0; i < 4; i++) {
                uint32_t addr = SA + SW128((wm + i * 16 + lrow16) * 128 + kbyte);
                LDSM_X4(afr[i], addr);
            }
            uint32_t bfr[4][4];
            #pragma unroll
            for (int j = 0; j < 4; j++) {
                uint32_t addr = SB + SW128((wn + j * 16 + lrow16) * 128 + kbyte);
                LDSM_X4(bfr[j], addr);
            }
            #pragma unroll
            for (int i = 0; i < 4; i++) {
                #pragma unroll
                for (int jj = 0; jj < 8; jj++) {
                    const int j = jj >> 1, o = jj & 1;
                    MMA16816(acc[i][jj], afr[i], bfr[j][o], bfr[j][o + 2]);
                }
            }
        }
        __syncthreads();
    }

    // ---- epilogue: register accums -> global
    const int mrow = lane >> 2;          // 0..7
    const int ncol = (lane & 3) * 2;     // 0,2,4,6
    #pragma unroll
    for (int i = 0; i < 4; i++) {
        #pragma unroll
        for (int jj = 0; jj < 8; jj++) {
            const int n = bx * 128 + wn + jj * 8 + ncol;
            #pragma unroll
            for (int h = 0; h < 2; h++) {  // row / row+8
                const long m = (long)by * 128 + wm + i * 16 + mrow + h * 8;
                const long off = bz * sC + m * ldc + n;
                float v0 = acc[i][jj][2 * h + 0];
                float v1 = acc[i][jj][2 * h + 1];
                if (EPI == 0) {
                    v0 += __ldg(&bias[n]);
                    v1 += __ldg(&bias[n + 1]);
                    __nv_bfloat16 h0 = __float2bfloat16(v0);
                    __nv_bfloat16 h1 = __float2bfloat16(v1);
                    __nv_bfloat16 l0 = __float2bfloat16(v0 - __bfloat162float(h0));
                    __nv_bfloat16 l1 = __float2bfloat16(v1 - __bfloat162float(h1));
                    *(__nv_bfloat162*)(Chi + off) = __halves2bfloat162(h0, h1);
                    *(__nv_bfloat162*)(Clo + off) = __halves2bfloat162(l0, l1);
                } else {
                    const float sc = (EPI == 1) ? kScale : 1.0f;
                    float2 v; v.x = v0 * sc; v.y = v1 * sc;
                    *(float2*)(Cf + off) = v;
                }
            }
        }
    }
}

// ---------------------------------------------------------------------------
// fp32 -> bf16 hi/lo split (elementwise)
// ---------------------------------------------------------------------------
__global__ __launch_bounds__(256) void split_kernel(
    const float* __restrict__ x, __nv_bfloat16* __restrict__ hi,
    __nv_bfloat16* __restrict__ lo)
{
    long i = ((long)blockIdx.x * 256 + threadIdx.x) * 4;
    float4 v = *(const float4*)(x + i);
    __nv_bfloat16 h0 = __float2bfloat16(v.x), h1 = __float2bfloat16(v.y);
    __nv_bfloat16 h2 = __float2bfloat16(v.z), h3 = __float2bfloat16(v.w);
    __nv_bfloat16 l0 = __float2bfloat16(v.x - __bfloat162float(h0));
    __nv_bfloat16 l1 = __float2bfloat16(v.y - __bfloat162float(h1));
    __nv_bfloat16 l2 = __float2bfloat16(v.z - __bfloat162float(h2));
    __nv_bfloat16 l3 = __float2bfloat16(v.w - __bfloat162float(h3));
    ((__nv_bfloat162*)(hi + i))[0] = __halves2bfloat162(h0, h1);
    ((__nv_bfloat162*)(hi + i))[1] = __halves2bfloat162(h2, h3);
    ((__nv_bfloat162*)(lo + i))[0] = __halves2bfloat162(l0, l1);
    ((__nv_bfloat162*)(lo + i))[1] = __halves2bfloat162(l2, l3);
}

// ---------------------------------------------------------------------------
// qh [b, Lq, D] fp32 -> qhT hi/lo [b, D, Lq] bf16 (transpose + split)
// ---------------------------------------------------------------------------
__global__ __launch_bounds__(256) void transpose_split_kernel(
    const float* __restrict__ src, __nv_bfloat16* __restrict__ hiT,
    __nv_bfloat16* __restrict__ loT)
{
    __shared__ float t[32][33];
    const int b = blockIdx.z;
    const int i = blockIdx.x;   // D/32
    const int j = blockIdx.y;   // Lq/32
    const int tx = threadIdx.x & 31, ty = threadIdx.x >> 5;

    const float* s = src + ((long)b * LQ + j * 32) * DIM + i * 32;
    #pragma unroll
    for (int r = 0; r < 4; r++)
        t[ty + 8 * r][tx] = s[(long)(ty + 8 * r) * DIM + tx];
    __syncthreads();

    const long dbase = ((long)b * DIM + i * 32) * LQ + j * 32;
    #pragma unroll
    for (int r = 0; r < 4; r++) {
        float v = t[tx][ty + 8 * r];
        __nv_bfloat16 h = __float2bfloat16(v);
        __nv_bfloat16 l = __float2bfloat16(v - __bfloat162float(h));
        hiT[dbase + (long)(ty + 8 * r) * LQ + tx] = h;
        loT[dbase + (long)(ty + 8 * r) * LQ + tx] = l;
    }
}

// ---------------------------------------------------------------------------
// Masked softmax over q (row len 1024); outputs P as bf16 hi/lo split
// ---------------------------------------------------------------------------
__global__ __launch_bounds__(256) void softmax_kernel(
    const float* __restrict__ S, const int* __restrict__ qmask,
    __nv_bfloat16* __restrict__ Phi, __nv_bfloat16* __restrict__ Plo)
{
    const int row = blockIdx.x;
    const int b = row >> 11;
    const float* s = S + (long)row * LQ;
    const int* msk = qmask + b * LQ;

    const int t = threadIdx.x;
    const int lane = t & 31, warp = t >> 5;

    float4 v = ((const float4*)s)[t];
    int4 m = ((const int4*)msk)[t];
    float x0 = m.x ? v.x : -1e30f;
    float x1 = m.y ? v.y : -1e30f;
    float x2 = m.z ? v.z : -1e30f;
    float x3 = m.w ? v.w : -1e30f;

    __shared__ float sh[8];
    __shared__ float shv[2];

    float mx = fmaxf(fmaxf(x0, x1), fmaxf(x2, x3));
    #pragma unroll
    for (int off = 16; off > 0; off >>= 1)
        mx = fmaxf(mx, __shfl_xor_sync(0xffffffffu, mx, off));
    if (lane == 0) sh[warp] = mx;
    __syncthreads();
    if (t == 0) {
        float r = sh[0];
        #pragma unroll
        for (int i = 1; i < 8; i++) r = fmaxf(r, sh[i]);
        shv[0] = r;
    }
    __syncthreads();
    mx = shv[0];

    float e0 = m.x ? __expf(x0 - mx) : 0.0f;
    float e1 = m.y ? __expf(x1 - mx) : 0.0f;
    float e2 = m.z ? __expf(x2 - mx) : 0.0f;
    float e3 = m.w ? __expf(x3 - mx) : 0.0f;
    float sum = e0 + e1 + e2 + e3;
    #pragma unroll
    for (int off = 16; off > 0; off >>= 1)
        sum += __shfl_xor_sync(0xffffffffu, sum, off);
    __syncthreads();
    if (lane == 0) sh[warp] = sum;
    __syncthreads();
    if (t == 0) {
        float r = 0.0f;
        #pragma unroll
        for (int i = 0; i < 8; i++) r += sh[i];
        shv[1] = r;
    }
    __syncthreads();
    float inv = 1.0f / shv[1];

    float p0 = e0 * inv, p1 = e1 * inv, p2 = e2 * inv, p3 = e3 * inv;
    __nv_bfloat16 h0 = __float2bfloat16(p0), h1 = __float2bfloat16(p1);
    __nv_bfloat16 h2 = __float2bfloat16(p2), h3 = __float2bfloat16(p3);
    __nv_bfloat16 l0 = __float2bfloat16(p0 - __bfloat162float(h0));
    __nv_bfloat16 l1 = __float2bfloat16(p1 - __bfloat162float(h1));
    __nv_bfloat16 l2 = __float2bfloat16(p2 - __bfloat162float(h2));
    __nv_bfloat16 l3 = __float2bfloat16(p3 - __bfloat162float(h3));
    long base = (long)row * LQ + t * 4;
    ((__nv_bfloat162*)(Phi + base))[0] = __halves2bfloat162(h0, h1);
    ((__nv_bfloat162*)(Phi + base))[1] = __halves2bfloat162(h2, h3);
    ((__nv_bfloat162*)(Plo + base))[0] = __halves2bfloat162(l0, l1);
    ((__nv_bfloat162*)(Plo + base))[1] = __halves2bfloat162(l2, l3);
}

// ---------------------------------------------------------------------------
// out[..., 0:768] = context_hiddens
// ---------------------------------------------------------------------------
__global__ __launch_bounds__(256) void copy_ctx_kernel(
    const float* __restrict__ chx, float* __restrict__ out)
{
    long idx = (long)blockIdx.x * blockDim.x + threadIdx.x;
    float4 v = ((const float4*)chx)[idx];
    long row = idx / 192;
    long c4 = idx % 192;
    ((float4*)out)[row * 384 + c4] = v;
}

// ---------------------------------------------------------------------------
extern "C" void kernel_launch(void* const* d_in, const int* in_sizes, int n_in,
                              void* d_out, int out_size)
{
    (void)in_sizes; (void)n_in; (void)out_size;
    const float* chx   = (const float*)d_in[0];
    const float* qh    = (const float*)d_in[2];
    const int*   qmask = (const int*)d_in[3];
    const float* W     = (const float*)d_in[4];
    const float* bvec  = (const float*)d_in[5];
    float* out = (float*)d_out;

    cudaFuncSetAttribute(gemm_mma<0>, cudaFuncAttributeMaxDynamicSharedMemorySize, SMEM_TOTAL);
    cudaFuncSetAttribute(gemm_mma<1>, cudaFuncAttributeMaxDynamicSharedMemorySize, SMEM_TOTAL);
    cudaFuncSetAttribute(gemm_mma<2>, cudaFuncAttributeMaxDynamicSharedMemorySize, SMEM_TOTAL);

    __nv_bfloat16 *ch_hi, *ch_lo, *qh_hi, *qh_lo, *qhT_hi, *qhT_lo;
    __nv_bfloat16 *W_hi, *W_lo, *q_hi, *q_lo, *p_hi, *p_lo;
    float* scores;
    cudaGetSymbolAddress((void**)&ch_hi,  g_ch_hi);
    cudaGetSymbolAddress((void**)&ch_lo,  g_ch_lo);
    cudaGetSymbolAddress((void**)&qh_hi,  g_qh_hi);
    cudaGetSymbolAddress((void**)&qh_lo,  g_qh_lo);
    cudaGetSymbolAddress((void**)&qhT_hi, g_qhT_hi);
    cudaGetSymbolAddress((void**)&qhT_lo, g_qhT_lo);
    cudaGetSymbolAddress((void**)&W_hi,   g_W_hi);
    cudaGetSymbolAddress((void**)&W_lo,   g_W_lo);
    cudaGetSymbolAddress((void**)&q_hi,   g_q_hi);
    cudaGetSymbolAddress((void**)&q_lo,   g_q_lo);
    cudaGetSymbolAddress((void**)&p_hi,   g_p_hi);
    cudaGetSymbolAddress((void**)&p_lo,   g_p_lo);
    cudaGetSymbolAddress((void**)&scores, g_scores);

    // splits
    split_kernel<<<12288, 256>>>(chx, ch_hi, ch_lo);
    split_kernel<<<6144, 256>>>(qh, qh_hi, qh_lo);
    split_kernel<<<576, 256>>>(W, W_hi, W_lo);
    transpose_split_kernel<<<dim3(DIM / 32, LQ / 32, NB), 256>>>(qh, qhT_hi, qhT_lo);

    // 1) query = qh @ W^T + b  -> split bf16   (M=8192, N=768, K=768)
    gemm_mma<0><<<dim3(6, 64, 1), 128, SMEM_TOTAL>>>(
        qh_hi, qh_lo, 0L, W_hi, W_lo, 0L,
        DIM, DIM, 0L, nullptr, q_hi, q_lo, bvec);

    // 2) scores = ch @ query^T * SCALE  (per b: M=2048, N=1024, K=768)
    gemm_mma<1><<<dim3(8, 16, NB), 128, SMEM_TOTAL>>>(
        ch_hi, ch_lo, (long)LC * DIM,
        q_hi, q_lo, (long)LQ * DIM,
        DIM, LQ, (long)LC * LQ, scores, nullptr, nullptr, nullptr);

    // 3) masked softmax -> P hi/lo
    softmax_kernel<<<NB * LC, 256>>>(scores, qmask, p_hi, p_lo);

    // 4) attn = P @ qh  (per b: M=2048, N=768, K=1024) -> out[..., 768:]
    gemm_mma<2><<<dim3(6, 16, NB), 128, SMEM_TOTAL>>>(
        p_hi, p_lo, (long)LC * LQ,
        qhT_hi, qhT_lo, (long)DIM * LQ,
        LQ, ODIM, (long)LC * ODIM, out + DIM, nullptr, nullptr, nullptr);

    // 5) out[..., 0:768] = context_hiddens
    copy_ctx_kernel<<<12288, 256>>>(chx, out);
}